// round 14
// baseline (speedup 1.0000x reference)
#include <cuda_runtime.h>
#include <cuda_fp16.h>
#include <cuda_fp8.h>
#include <cstdint>

// Problem shapes (fixed by the dataset)
#define M_FULL  16384
#define N_DIM   4096
#define K_DIM   4096

// Scratch (allocation-free rule: __device__ globals)
__device__ __half g_A16[(size_t)(M_FULL / 2) * K_DIM];  // fp16 Asum [M][K]
__device__ __half g_B16[(size_t)K_DIM * N_DIM];          // fp16 B^T [N][K]
__device__ int    g_tile_ctr;                            // persistent-GEMM work queue

// ---------------------------------------------------------------------------
// fp8 helpers
// ---------------------------------------------------------------------------
__device__ __forceinline__ float fp8_round(float x) {
    __nv_fp8_storage_t s = __nv_cvt_float_to_fp8(x, __NV_SATFINITE, __NV_E4M3);
    __half_raw hr = __nv_cvt_fp8_to_halfraw(s, __NV_E4M3);
    return __half2float(__half(hr));
}
__device__ __forceinline__ __half fp8_to_half(float x) {
    __nv_fp8_storage_t s = __nv_cvt_float_to_fp8(x, __NV_SATFINITE, __NV_E4M3);
    __half_raw hr = __nv_cvt_fp8_to_halfraw(s, __NV_E4M3);  // e4m3 exact in fp16
    return __half(hr);
}

// ---------------------------------------------------------------------------
// Fused prep kernel:
//   part 1 (blocks [0, rblocks)): Asum = sum_w fp8round(A_w), fp32 acc -> fp16
//   part 2 (rest):               W [K][N] f32 -> g_B16 = B^T [N][K] fp16
//   Also resets the persistent-GEMM tile counter (stream-ordered before GEMM).
// ---------------------------------------------------------------------------
__global__ __launch_bounds__(256)
void prep_kernel(const float* __restrict__ A, const float* __restrict__ W,
                 int shard4, int world, int rblocks) {
    if (blockIdx.x == 0 && threadIdx.x == 0) g_tile_ctr = 0;
    if ((int)blockIdx.x < rblocks) {
        int idx = blockIdx.x * 256 + threadIdx.x;
        if (idx >= shard4) return;
        const float4* A4 = (const float4*)A;
        float4 s = make_float4(0.f, 0.f, 0.f, 0.f);
        for (int w = 0; w < world; w++) {
            float4 v = A4[(size_t)w * shard4 + idx];
            s.x += fp8_round(v.x);
            s.y += fp8_round(v.y);
            s.z += fp8_round(v.z);
            s.w += fp8_round(v.w);
        }
        ((__half2*)g_A16)[idx * 2 + 0] = __floats2half2_rn(s.x, s.y);
        ((__half2*)g_A16)[idx * 2 + 1] = __floats2half2_rn(s.z, s.w);
    } else {
        __shared__ float t[32][33];
        int q = blockIdx.x - rblocks;              // 0 .. 128*128-1
        int n0 = (q & 127) * 32;
        int k0 = (q >> 7) * 32;
        int tx = threadIdx.x & 31, ty = threadIdx.x >> 5;   // (32, 8)
#pragma unroll
        for (int i = 0; i < 4; i++)
            t[ty + 8 * i][tx] = W[(size_t)(k0 + ty + 8 * i) * N_DIM + n0 + tx];
        __syncthreads();
#pragma unroll
        for (int i = 0; i < 4; i++)
            g_B16[(size_t)(n0 + ty + 8 * i) * K_DIM + k0 + tx] = fp8_to_half(t[tx][ty + 8 * i]);
    }
}

// ---------------------------------------------------------------------------
// PTX helpers (sm_80-era instructions; valid on compute_103)
// ---------------------------------------------------------------------------
__device__ __forceinline__ uint32_t smem_u32(const void* p) {
    uint32_t a;
    asm("{ .reg .u64 t; cvta.to.shared.u64 t, %1; cvt.u32.u64 %0, t; }" : "=r"(a) : "l"(p));
    return a;
}
__device__ __forceinline__ void ldsm_x4(uint32_t& r0, uint32_t& r1, uint32_t& r2, uint32_t& r3,
                                        uint32_t addr) {
    asm volatile("ldmatrix.sync.aligned.m8n8.x4.shared.b16 {%0,%1,%2,%3}, [%4];"
                 : "=r"(r0), "=r"(r1), "=r"(r2), "=r"(r3) : "r"(addr));
}
__device__ __forceinline__ void mma_16816(float* c, const uint32_t* a, uint32_t b0, uint32_t b1) {
    asm volatile("mma.sync.aligned.m16n8k16.row.col.f32.f16.f16.f32 "
                 "{%0,%1,%2,%3}, {%4,%5,%6,%7}, {%8,%9}, {%0,%1,%2,%3};"
                 : "+f"(c[0]), "+f"(c[1]), "+f"(c[2]), "+f"(c[3])
                 : "r"(a[0]), "r"(a[1]), "r"(a[2]), "r"(a[3]), "r"(b0), "r"(b1));
}
__device__ __forceinline__ void cp16(uint32_t smem, const void* g) {
    asm volatile("cp.async.cg.shared.global [%0], [%1], 16;" :: "r"(smem), "l"(g) : "memory");
}
#define CP_COMMIT() asm volatile("cp.async.commit_group;" ::: "memory")
#define CP_WAIT(n)  asm volatile("cp.async.wait_group %0;" :: "n"(n) : "memory")

// ---------------------------------------------------------------------------
// Persistent GEMM: 64x128 tiles via atomic work stealing, 128 threads
// (4 warps, warp tile 32x64), BK=64, 3-stage cp.async, 2 CTAs/SM,
// fused scale_b + fp16-round epilogue.
// ---------------------------------------------------------------------------
#define BM 64
#define BN 128
#define BKH 64                        // halves per stage chunk (128 B rows)
#define STAGES 3
#define ROWB 128                      // bytes per smem row
#define A_STAGE (BM * ROWB)           // 8 KB
#define B_STAGE (BN * ROWB)           // 16 KB
#define STAGE_BYTES (A_STAGE + B_STAGE)
#define GEMM_SMEM (STAGES * STAGE_BYTES)   // 72 KB -> 2 CTAs/SM
#define NWORKERS 296                  // 2 x 148 SMs

__device__ __forceinline__ uint32_t sw_off(int row, int chunk) {
    return (uint32_t)(row * ROWB + ((chunk ^ (row & 7)) << 4));
}

__global__ __launch_bounds__(128, 2)
void gemm_mma_kernel(const float* __restrict__ scale_b, float* __restrict__ out,
                     int mtiles) {
    extern __shared__ char sm[];
    const uint32_t sbase = smem_u32(sm);

    const int tid  = threadIdx.x;
    const int lane = tid & 31;
    const int warp = tid >> 5;        // 0..3
    const int wm   = warp & 1;        // 0..1 -> 32-row group
    const int wn   = warp >> 1;       // 0..1 -> 64-col group

    // cp.async mapping: thread owns chunk (tid&7), base row tid>>3 (0..15)
    const int crow = tid >> 3;
    const int cchk = tid & 7;

    const int KITER = K_DIM / BKH;    // 64
    const int arow = wm * 32 + (lane & 15);
    const int brow = wn * 64 + (lane & 15);
    const int chsel = lane >> 4;
    const int ntiles = mtiles * (N_DIM / BN);

    __shared__ int s_tile;

    for (;;) {
        if (tid == 0) s_tile = atomicAdd(&g_tile_ctr, 1);
        __syncthreads();
        const int t = s_tile;
        if (t >= ntiles) break;

        // t -> (tm, tn): consecutive grabs share tm (A tile stays L2/L1-hot)
        const int tm = t >> 5;                   // N_DIM/BN == 32
        const int tn = t & 31;
        const int bm = tm * BM;
        const int bn = tn * BN;

        const __half* Ag = g_A16 + (size_t)bm * K_DIM;
        const __half* Bg = g_B16 + (size_t)bn * K_DIM;

        float acc[2][8][4] = {};      // [mi][n8][reg] -> 64 regs

        // Prologue: fill stages 0..STAGES-2
#pragma unroll
        for (int s = 0; s < STAGES - 1; s++) {
            const __half* ga = Ag + (size_t)s * BKH + cchk * 8;
            const __half* gb = Bg + (size_t)s * BKH + cchk * 8;
            uint32_t as = sbase + s * STAGE_BYTES;
            uint32_t bs = as + A_STAGE;
#pragma unroll
            for (int i = 0; i < 4; i++)
                cp16(as + sw_off(crow + i * 16, cchk), ga + (size_t)(crow + i * 16) * K_DIM);
#pragma unroll
            for (int i = 0; i < 8; i++)
                cp16(bs + sw_off(crow + i * 16, cchk), gb + (size_t)(crow + i * 16) * K_DIM);
            CP_COMMIT();
        }

        for (int it = 0; it < KITER; it++) {
            CP_WAIT(STAGES - 2);
            __syncthreads();          // stage it ready; refill target free

            const uint32_t As = sbase + (it % STAGES) * STAGE_BYTES;
            const uint32_t Bs = As + A_STAGE;

            const int nk = it + STAGES - 1;
            const bool do_ld = (nk < KITER);
            if (do_ld) {
                const __half* ga = Ag + (size_t)nk * BKH + cchk * 8;
                const __half* gb = Bg + (size_t)nk * BKH + cchk * 8;
                const uint32_t nas = sbase + (nk % STAGES) * STAGE_BYTES;
                const uint32_t nbs = nas + A_STAGE;
#pragma unroll
                for (int i = 0; i < 4; i++)
                    cp16(nas + sw_off(crow + i * 16, cchk), ga + (size_t)(crow + i * 16) * K_DIM);
#pragma unroll
                for (int i = 0; i < 8; i++)
                    cp16(nbs + sw_off(crow + i * 16, cchk), gb + (size_t)(crow + i * 16) * K_DIM);
            }
            CP_COMMIT();

#pragma unroll
            for (int ks = 0; ks < 4; ks++) {
                const int ch = ks * 2 + chsel;
                uint32_t a[2][4];
#pragma unroll
                for (int mi = 0; mi < 2; mi++)
                    ldsm_x4(a[mi][0], a[mi][1], a[mi][2], a[mi][3],
                            As + sw_off(arow + mi * 16, ch));
                uint32_t b[4][4];
#pragma unroll
                for (int nj = 0; nj < 4; nj++)
                    ldsm_x4(b[nj][0], b[nj][1], b[nj][2], b[nj][3],
                            Bs + sw_off(brow + nj * 16, ch));
#pragma unroll
                for (int mi = 0; mi < 2; mi++)
#pragma unroll
                    for (int n8 = 0; n8 < 8; n8++) {
                        int nj = n8 >> 1, hi = n8 & 1;
                        mma_16816(acc[mi][n8], a[mi], b[nj][hi], b[nj][hi + 2]);
                    }
            }
        }

        // Drain pipeline before next tile reuses smem
        CP_WAIT(0);
        __syncthreads();

        // Fused epilogue: scale_b + fp16 quantize, store fp32
#pragma unroll
        for (int mi = 0; mi < 2; mi++) {
#pragma unroll
            for (int n8 = 0; n8 < 8; n8++) {
                const float* c = acc[mi][n8];
                int row = bm + wm * 32 + mi * 16 + (lane >> 2);
                int col = bn + wn * 64 + n8 * 8 + (lane & 3) * 2;
                float2 s0 = *(const float2*)&scale_b[col];
                float2 v0;
                v0.x = __half2float(__float2half(c[0] * s0.x));
                v0.y = __half2float(__float2half(c[1] * s0.y));
                *(float2*)&out[(size_t)row * N_DIM + col] = v0;
                float2 v1;
                v1.x = __half2float(__float2half(c[2] * s0.x));
                v1.y = __half2float(__float2half(c[3] * s0.y));
                *(float2*)&out[(size_t)(row + 8) * N_DIM + col] = v1;
            }
        }
    }
}

// ---------------------------------------------------------------------------
// Host
// ---------------------------------------------------------------------------
extern "C" void kernel_launch(void* const* d_in, const int* in_sizes, int n_in,
                              void* d_out, int out_size) {
    const float* input = nullptr; const float* weight = nullptr; const float* scale_b = nullptr;
    long long input_elems = 0;
    for (int i = 0; i < n_in; i++) {
        long long sz = in_sizes[i];
        if (sz == (long long)K_DIM * N_DIM && !weight)      weight = (const float*)d_in[i];
        else if (sz == N_DIM && !scale_b)                   scale_b = (const float*)d_in[i];
        else if (sz > (long long)K_DIM * N_DIM)             { input = (const float*)d_in[i]; input_elems = sz; }
    }
    float* out = (float*)d_out;   // harness output buffer is FLOAT32

    long long M_full   = input_elems / K_DIM;
    long long out_rows = (long long)out_size / N_DIM;
    int world = (int)(M_full / (out_rows > 0 ? out_rows : M_full));
    if (world < 1) world = 1;
    int M_out = (int)(M_full / world);

    {
        int shard4 = (M_out * K_DIM) / 4;
        int rblocks = (shard4 + 255) / 256;
        int tblocks = (N_DIM / 32) * (K_DIM / 32);
        prep_kernel<<<rblocks + tblocks, 256>>>(input, weight, shard4, world, rblocks);
    }
    {
        cudaFuncSetAttribute(gemm_mma_kernel, cudaFuncAttributeMaxDynamicSharedMemorySize,
                             GEMM_SMEM);
        int mtiles = M_out / BM;
        gemm_mma_kernel<<<NWORKERS, 128, GEMM_SMEM>>>(scale_b, out, mtiles);
    }
}

// round 15
// speedup vs baseline: 1.4479x; 1.4479x over previous
#include <cuda_runtime.h>
#include <cuda_fp16.h>
#include <cuda_fp8.h>
#include <cstdint>

// Problem shapes (fixed by the dataset)
#define M_FULL  16384
#define N_DIM   4096
#define K_DIM   4096

// Scratch (allocation-free rule: __device__ globals)
__device__ __half g_A16[(size_t)(M_FULL / 2) * K_DIM];  // fp16 Asum [M][K]
__device__ __half g_B16[(size_t)K_DIM * N_DIM];          // fp16 B^T [N][K]
__device__ int    g_tiles;                               // phase-B work queue
__device__ int    g_bar;                                 // grid barrier (monotonic)

#define NCTA 148

// ---------------------------------------------------------------------------
// fp8 helpers
// ---------------------------------------------------------------------------
__device__ __forceinline__ float fp8_round(float x) {
    __nv_fp8_storage_t s = __nv_cvt_float_to_fp8(x, __NV_SATFINITE, __NV_E4M3);
    __half_raw hr = __nv_cvt_fp8_to_halfraw(s, __NV_E4M3);
    return __half2float(__half(hr));
}
__device__ __forceinline__ __half fp8_to_half(float x) {
    __nv_fp8_storage_t s = __nv_cvt_float_to_fp8(x, __NV_SATFINITE, __NV_E4M3);
    __half_raw hr = __nv_cvt_fp8_to_halfraw(s, __NV_E4M3);  // e4m3 exact in fp16
    return __half(hr);
}

// ---------------------------------------------------------------------------
// PTX helpers (sm_80-era instructions; valid on compute_103)
// ---------------------------------------------------------------------------
__device__ __forceinline__ uint32_t smem_u32(const void* p) {
    uint32_t a;
    asm("{ .reg .u64 t; cvta.to.shared.u64 t, %1; cvt.u32.u64 %0, t; }" : "=r"(a) : "l"(p));
    return a;
}
__device__ __forceinline__ void ldsm_x4(uint32_t& r0, uint32_t& r1, uint32_t& r2, uint32_t& r3,
                                        uint32_t addr) {
    asm volatile("ldmatrix.sync.aligned.m8n8.x4.shared.b16 {%0,%1,%2,%3}, [%4];"
                 : "=r"(r0), "=r"(r1), "=r"(r2), "=r"(r3) : "r"(addr));
}
__device__ __forceinline__ void mma_16816(float* c, const uint32_t* a, uint32_t b0, uint32_t b1) {
    asm volatile("mma.sync.aligned.m16n8k16.row.col.f32.f16.f16.f32 "
                 "{%0,%1,%2,%3}, {%4,%5,%6,%7}, {%8,%9}, {%0,%1,%2,%3};"
                 : "+f"(c[0]), "+f"(c[1]), "+f"(c[2]), "+f"(c[3])
                 : "r"(a[0]), "r"(a[1]), "r"(a[2]), "r"(a[3]), "r"(b0), "r"(b1));
}
__device__ __forceinline__ void cp16(uint32_t smem, const void* g) {
    asm volatile("cp.async.cg.shared.global [%0], [%1], 16;" :: "r"(smem), "l"(g) : "memory");
}
#define CP_COMMIT() asm volatile("cp.async.commit_group;" ::: "memory")
#define CP_WAIT(n)  asm volatile("cp.async.wait_group %0;" :: "n"(n) : "memory")

// ---------------------------------------------------------------------------
// GEMM tile config (R12-proven): 128x256 CTA tile, 8 warps (64x64 warp tile),
// BK=64, 4-stage cp.async ring, register double-buffered fragments.
// ---------------------------------------------------------------------------
#define BM 128
#define BN 256
#define BKH 64
#define STAGES 4
#define ROWB 128
#define A_STAGE (BM * ROWB)           // 16 KB
#define B_STAGE (BN * ROWB)           // 32 KB
#define STAGE_BYTES (A_STAGE + B_STAGE)
#define GEMM_SMEM (STAGES * STAGE_BYTES)   // 192 KB, 1 CTA/SM

__device__ __forceinline__ uint32_t sw_off(int row, int chunk) {
    return (uint32_t)(row * ROWB + ((chunk ^ (row & 7)) << 4));
}

// ---------------------------------------------------------------------------
// Persistent mega-kernel: Phase A (prep) -> grid barrier -> Phase B (GEMM)
// ---------------------------------------------------------------------------
__global__ __launch_bounds__(256)
void mega_kernel(const float* __restrict__ A, const float* __restrict__ W,
                 const float* __restrict__ scale_b, float* __restrict__ out,
                 int shard4, int world, int ntiles) {
    extern __shared__ char sm[];
    const uint32_t sbase = smem_u32(sm);
    const int tid = threadIdx.x;

    // ======================= PHASE A: prep ================================
    if (blockIdx.x == 0 && tid == 0) g_tiles = 0;    // queue reset (pre-barrier)

    // A.1: Asum = sum_w fp8round(A_w) -> fp16   (thread grid-stride)
    {
        const float4* A4 = (const float4*)A;
        for (int idx = blockIdx.x * 256 + tid; idx < shard4; idx += NCTA * 256) {
            float4 s = make_float4(0.f, 0.f, 0.f, 0.f);
            for (int w = 0; w < world; w++) {
                float4 v = A4[(size_t)w * shard4 + idx];
                s.x += fp8_round(v.x);
                s.y += fp8_round(v.y);
                s.z += fp8_round(v.z);
                s.w += fp8_round(v.w);
            }
            ((__half2*)g_A16)[idx * 2 + 0] = __floats2half2_rn(s.x, s.y);
            ((__half2*)g_A16)[idx * 2 + 1] = __floats2half2_rn(s.z, s.w);
        }
    }

    // A.2: W [K][N] f32 -> g_B16 = B^T [N][K] fp16   (CTA grid-stride, 32x32 tiles)
    {
        float (*t)[33] = (float(*)[33])sm;           // reuse dynamic smem
        const int TT = (N_DIM / 32) * (K_DIM / 32);  // 16384 tiles
        int tx = tid & 31, ty = tid >> 5;            // (32, 8)
        for (int q = blockIdx.x; q < TT; q += NCTA) {
            int n0 = (q & 127) * 32;
            int k0 = (q >> 7) * 32;
            __syncthreads();
#pragma unroll
            for (int i = 0; i < 4; i++)
                t[ty + 8 * i][tx] = W[(size_t)(k0 + ty + 8 * i) * N_DIM + n0 + tx];
            __syncthreads();
#pragma unroll
            for (int i = 0; i < 4; i++)
                g_B16[(size_t)(n0 + ty + 8 * i) * K_DIM + k0 + tx] =
                    fp8_to_half(t[tx][ty + 8 * i]);
        }
    }

    // ===================== grid barrier (replay-safe) =====================
    __threadfence();
    __syncthreads();
    if (tid == 0) {
        int a = atomicAdd(&g_bar, 1) + 1;            // my global arrival number
        int tgt = ((a + NCTA - 1) / NCTA) * NCTA;    // this launch's release value
        while (*(volatile int*)&g_bar < tgt) { }
    }
    __syncthreads();
    __threadfence();

    // ======================= PHASE B: GEMM ================================
    const int lane = tid & 31;
    const int warp = tid >> 5;        // 0..7
    const int wm   = warp & 1;        // 0..1 -> 64-row group
    const int wn   = warp >> 1;       // 0..3 -> 64-col group
    const int crow = tid >> 3;        // cp.async row base (0..31)
    const int cchk = tid & 7;
    const int KITER = K_DIM / BKH;    // 64
    const int arow = wm * 64 + (lane & 15);
    const int brow = wn * 64 + (lane & 15);
    const int chsel = lane >> 4;

    __shared__ int s_tile;
    uint32_t af[2][4][4];
    uint32_t bf[2][4][4];

    for (;;) {
        __syncthreads();
        if (tid == 0) s_tile = atomicAdd(&g_tiles, 1);
        __syncthreads();
        const int t = s_tile;
        if (t >= ntiles) break;

        const int tm = t >> 4;                   // N_DIM/BN == 16
        const int tn = t & 15;
        const int bm = tm * BM;
        const int bn = tn * BN;

        const __half* Ag = g_A16 + (size_t)bm * K_DIM;
        const __half* Bg = g_B16 + (size_t)bn * K_DIM;

        float acc[4][8][4] = {};

        // Prologue: fill stages 0..STAGES-2
#pragma unroll
        for (int s = 0; s < STAGES - 1; s++) {
            const __half* ga = Ag + (size_t)s * BKH + cchk * 8;
            const __half* gb = Bg + (size_t)s * BKH + cchk * 8;
            uint32_t as = sbase + s * STAGE_BYTES;
            uint32_t bs = as + A_STAGE;
#pragma unroll
            for (int i = 0; i < 4; i++)
                cp16(as + sw_off(crow + i * 32, cchk), ga + (size_t)(crow + i * 32) * K_DIM);
#pragma unroll
            for (int i = 0; i < 8; i++)
                cp16(bs + sw_off(crow + i * 32, cchk), gb + (size_t)(crow + i * 32) * K_DIM);
            CP_COMMIT();
        }

        for (int it = 0; it < KITER; it++) {
            CP_WAIT(STAGES - 2);
            __syncthreads();

            const uint32_t As = sbase + (it % STAGES) * STAGE_BYTES;
            const uint32_t Bs = As + A_STAGE;

            const int nk = it + STAGES - 1;
            const bool do_ld = (nk < KITER);
            const __half* ga = Ag + (size_t)nk * BKH + cchk * 8;
            const __half* gb = Bg + (size_t)nk * BKH + cchk * 8;
            const uint32_t nas = sbase + (nk % STAGES) * STAGE_BYTES;
            const uint32_t nbs = nas + A_STAGE;

            // Preload ks=0 fragments into buffer 0
            {
                const int ch = chsel;
#pragma unroll
                for (int mi = 0; mi < 4; mi++)
                    ldsm_x4(af[0][mi][0], af[0][mi][1], af[0][mi][2], af[0][mi][3],
                            As + sw_off(arow + mi * 16, ch));
#pragma unroll
                for (int nj = 0; nj < 4; nj++)
                    ldsm_x4(bf[0][nj][0], bf[0][nj][1], bf[0][nj][2], bf[0][nj][3],
                            Bs + sw_off(brow + nj * 16, ch));
            }

#pragma unroll
            for (int ks = 0; ks < 4; ks++) {
                const int cur = ks & 1;
                const int nxt = cur ^ 1;

                if (ks < 3) {
                    const int ch = (ks + 1) * 2 + chsel;
#pragma unroll
                    for (int mi = 0; mi < 4; mi++)
                        ldsm_x4(af[nxt][mi][0], af[nxt][mi][1], af[nxt][mi][2], af[nxt][mi][3],
                                As + sw_off(arow + mi * 16, ch));
#pragma unroll
                    for (int nj = 0; nj < 4; nj++)
                        ldsm_x4(bf[nxt][nj][0], bf[nxt][nj][1], bf[nxt][nj][2], bf[nxt][nj][3],
                                Bs + sw_off(brow + nj * 16, ch));
                }

                if (do_ld) {
                    int r = crow + ks * 32;
                    cp16(nas + sw_off(r, cchk), ga + (size_t)r * K_DIM);
                    int r0 = crow + (ks * 2) * 32;
                    int r1 = crow + (ks * 2 + 1) * 32;
                    cp16(nbs + sw_off(r0, cchk), gb + (size_t)r0 * K_DIM);
                    cp16(nbs + sw_off(r1, cchk), gb + (size_t)r1 * K_DIM);
                }
                if (ks == 3) CP_COMMIT();

#pragma unroll
                for (int mi = 0; mi < 4; mi++)
#pragma unroll
                    for (int n8 = 0; n8 < 8; n8++) {
                        int nj = n8 >> 1, hi = n8 & 1;
                        mma_16816(acc[mi][n8], af[cur][mi], bf[cur][nj][hi], bf[cur][nj][hi + 2]);
                    }
            }
        }

        // Drain before smem reuse by next tile
        CP_WAIT(0);

        // Fused epilogue: scale_b + fp16 quantize, store fp32
#pragma unroll
        for (int mi = 0; mi < 4; mi++) {
#pragma unroll
            for (int n8 = 0; n8 < 8; n8++) {
                const float* c = acc[mi][n8];
                int row = bm + wm * 64 + mi * 16 + (lane >> 2);
                int col = bn + wn * 64 + n8 * 8 + (lane & 3) * 2;
                float2 s0 = *(const float2*)&scale_b[col];
                float2 v0;
                v0.x = __half2float(__float2half(c[0] * s0.x));
                v0.y = __half2float(__float2half(c[1] * s0.y));
                *(float2*)&out[(size_t)row * N_DIM + col] = v0;
                float2 v1;
                v1.x = __half2float(__float2half(c[2] * s0.x));
                v1.y = __half2float(__float2half(c[3] * s0.y));
                *(float2*)&out[(size_t)(row + 8) * N_DIM + col] = v1;
            }
        }
    }
}

// ---------------------------------------------------------------------------
// Host
// ---------------------------------------------------------------------------
extern "C" void kernel_launch(void* const* d_in, const int* in_sizes, int n_in,
                              void* d_out, int out_size) {
    const float* input = nullptr; const float* weight = nullptr; const float* scale_b = nullptr;
    long long input_elems = 0;
    for (int i = 0; i < n_in; i++) {
        long long sz = in_sizes[i];
        if (sz == (long long)K_DIM * N_DIM && !weight)      weight = (const float*)d_in[i];
        else if (sz == N_DIM && !scale_b)                   scale_b = (const float*)d_in[i];
        else if (sz > (long long)K_DIM * N_DIM)             { input = (const float*)d_in[i]; input_elems = sz; }
    }
    float* out = (float*)d_out;   // harness output buffer is FLOAT32

    long long M_full   = input_elems / K_DIM;
    long long out_rows = (long long)out_size / N_DIM;
    int world = (int)(M_full / (out_rows > 0 ? out_rows : M_full));
    if (world < 1) world = 1;
    int M_out = (int)(M_full / world);

    int shard4 = (M_out * K_DIM) / 4;
    int ntiles = (M_out / BM) * (N_DIM / BN);

    cudaFuncSetAttribute(mega_kernel, cudaFuncAttributeMaxDynamicSharedMemorySize, GEMM_SMEM);
    mega_kernel<<<NCTA, 256, GEMM_SMEM>>>(input, weight, scale_b, out,
                                          shard4, world, ntiles);
}